// round 16
// baseline (speedup 1.0000x reference)
#include <cuda_runtime.h>
#include <cuda_bf16.h>
#include <math.h>

// InnerCos: mean over rows of clamp(1 - cos_sim(x_i, centers[label_i]))
// x: [N, 256] f32, label: [N] i32, centers: [C, 256] f32 -> scalar f32
// Single-node graph: fence-free last-block finalize (atomics only, no CCTL.IVALL).

#define D_DIM 256
#define THREADS 256               // 8 warps
#define NW (THREADS / 32)
#define GROUPS 2                  // register double-buffer ping-pong
#define GROUP_ROWS 32             // 8 warps * 4 rows
#define ROWS_PER_BLOCK (GROUPS * GROUP_ROWS)   // 64 -> grid 4096 for N=256K

__device__ float g_sum   = 0.0f;  // cross-CTA accumulator (self-resetting)
__device__ int   g_count = 0;     // completed-CTA counter (self-resetting)

__device__ __forceinline__ float4 ldcs4(const float4* p) {
    return __ldcs(p);             // streaming: x bytes are read exactly once
}

// ---- Main: 8 lanes/row, 4 rows/warp, register double-buffer ----
// ALL_VALID=true when N % ROWS_PER_BLOCK == 0 (no bounds checks at all).
template <bool ALL_VALID>
__global__ void __launch_bounds__(THREADS, 3)
inner_cos_kernel(const float* __restrict__ x,
                 const int* __restrict__ lab,
                 const float* __restrict__ cen,
                 float* __restrict__ out,
                 int N, float invN)
{
    const int tid  = threadIdx.x;
    const int lane = tid & 31;
    const int warp = tid >> 5;
    const int sub  = lane >> 3;   // warp's row 0..3 within a group
    const int sl   = lane & 7;    // owns 8 float4 of the row

    const int rbase = blockIdx.x * ROWS_PER_BLOCK + warp * 4 + sub;

    float acc = 0.0f;

    // ---- pipeline prologue: group 0 loads ----
    const int r0 = rbase;
    int lb = (ALL_VALID || r0 < N) ? __ldg(lab + r0) : 0;
    float4 a[8];
    {
        const int rc = ALL_VALID ? r0 : min(r0, N - 1);
        const float4* xr = reinterpret_cast<const float4*>(x + (size_t)rc * D_DIM);
        #pragma unroll
        for (int j = 0; j < 8; ++j)
            a[j] = ldcs4(xr + sl + 8 * j);
    }

    #pragma unroll
    for (int it = 0; it < GROUPS; ++it) {
        const bool v      = ALL_VALID || (rbase + it * GROUP_ROWS) < N;
        const int  lb_cur = lb;

        // ---- issue NEXT group's loads first (keep DRAM queue full) ----
        float4 b[8];
        if (it + 1 < GROUPS) {
            const int rn = rbase + (it + 1) * GROUP_ROWS;
            lb = (ALL_VALID || rn < N) ? __ldg(lab + rn) : 0;
            const int rc = ALL_VALID ? rn : min(rn, N - 1);
            const float4* xn = reinterpret_cast<const float4*>(x + (size_t)rc * D_DIM);
            #pragma unroll
            for (int j = 0; j < 8; ++j)
                b[j] = ldcs4(xn + sl + 8 * j);
        }

        // ---- compute on CURRENT group: dot, ||x||^2, ||c||^2 inline ----
        const float4* cr = reinterpret_cast<const float4*>(
            cen + (size_t)lb_cur * D_DIM);

        float dot0 = 0.f, dot1 = 0.f, nx0 = 0.f, nx1 = 0.f, nc0 = 0.f, nc1 = 0.f;
        #pragma unroll
        for (int j = 0; j < 8; j += 2) {
            float4 c0 = __ldg(cr + sl + 8 * j);        // L1-resident
            float4 c1 = __ldg(cr + sl + 8 * (j + 1));
            dot0 = fmaf(a[j].x, c0.x, fmaf(a[j].y, c0.y,
                   fmaf(a[j].z, c0.z, fmaf(a[j].w, c0.w, dot0))));
            nx0  = fmaf(a[j].x, a[j].x, fmaf(a[j].y, a[j].y,
                   fmaf(a[j].z, a[j].z, fmaf(a[j].w, a[j].w, nx0))));
            nc0  = fmaf(c0.x, c0.x, fmaf(c0.y, c0.y,
                   fmaf(c0.z, c0.z, fmaf(c0.w, c0.w, nc0))));
            dot1 = fmaf(a[j+1].x, c1.x, fmaf(a[j+1].y, c1.y,
                   fmaf(a[j+1].z, c1.z, fmaf(a[j+1].w, c1.w, dot1))));
            nx1  = fmaf(a[j+1].x, a[j+1].x, fmaf(a[j+1].y, a[j+1].y,
                   fmaf(a[j+1].z, a[j+1].z, fmaf(a[j+1].w, a[j+1].w, nx1))));
            nc1  = fmaf(c1.x, c1.x, fmaf(c1.y, c1.y,
                   fmaf(c1.z, c1.z, fmaf(c1.w, c1.w, nc1))));
        }
        float dot = dot0 + dot1;
        float nx2 = nx0 + nx1;
        float nc2 = nc0 + nc1;

        #pragma unroll
        for (int o = 4; o > 0; o >>= 1) {      // reduce across the 8-lane group
            dot += __shfl_xor_sync(0xffffffffu, dot, o);
            nx2 += __shfl_xor_sync(0xffffffffu, nx2, o);
            nc2 += __shfl_xor_sync(0xffffffffu, nc2, o);
        }

        if (sl == 0 && v) {
            // cos = dot / max(||x||*||c||, 1e-8)  ==  dot * rsqrt(max(nx2*nc2, 1e-16))
            float cos = dot * rsqrtf(fmaxf(nx2 * nc2, 1e-16f));
            acc += fminf(fmaxf(1.0f - cos, 1e-12f), 1e12f);
        }

        // ---- rotate pipeline ----
        if (it + 1 < GROUPS) {
            #pragma unroll
            for (int j = 0; j < 8; ++j) a[j] = b[j];
        }
    }

    // ---- warp reduce (acc nonzero only on sl==0 lanes), block reduce ----
    #pragma unroll
    for (int o = 16; o > 0; o >>= 1)
        acc += __shfl_xor_sync(0xffffffffu, acc, o);

    __shared__ float wsum[NW];
    if (lane == 0) wsum[warp] = acc;
    __syncthreads();

    // ---- fence-free cross-CTA finalize: atomics only (all at L2) ----
    if (tid == 0) {
        float s = 0.0f;
        #pragma unroll
        for (int i = 0; i < NW; ++i) s += wsum[i];

        // Sum atomic WITH return value: thread stalls until committed at L2.
        float old = atomicAdd(&g_sum, s);

        // Data-dependent increment (always 1; compiler cannot fold a runtime
        // comparison) -> count atomic cannot issue before sum atomic completed.
        // g_sum only ever holds 0 or a finite positive sum, never this NaN bit
        // pattern, so inc == 1 always.
        int inc = (__float_as_int(old) == 0x7fc00123) ? 2 : 1;
        int done = atomicAdd(&g_count, inc);

        if (done == (int)gridDim.x - 1) {
            // All CTAs' sums are committed at L2 (each count increment was
            // data-dependent on its sum commit; L2 serializes per address).
            float total = atomicExch(&g_sum, 0.0f);   // read + reset in one op
            *out = total * invN;
            atomicExch(&g_count, 0);                  // reset for next replay
        }
    }
}

extern "C" void kernel_launch(void* const* d_in, const int* in_sizes, int n_in,
                              void* d_out, int out_size)
{
    const float* x   = (const float*)d_in[0];   // ref_emb [N, 256]
    const int*   lab = (const int*)d_in[1];     // ref_label [N]
    const float* cen = (const float*)d_in[2];   // centers [C, 256]
    float* out = (float*)d_out;

    const int N = in_sizes[1];
    const int blocks = (N + ROWS_PER_BLOCK - 1) / ROWS_PER_BLOCK;
    const float invN = 1.0f / (float)N;

    if (N % ROWS_PER_BLOCK == 0)
        inner_cos_kernel<true><<<blocks, THREADS>>>(x, lab, cen, out, N, invN);
    else
        inner_cos_kernel<false><<<blocks, THREADS>>>(x, lab, cen, out, N, invN);
}

// round 17
// speedup vs baseline: 1.0285x; 1.0285x over previous
#include <cuda_runtime.h>
#include <cuda_bf16.h>
#include <math.h>

// InnerCos: mean over rows of clamp(1 - cos_sim(x_i, centers[label_i]))
// x: [N, 256] f32, label: [N] i32, centers: [C, 256] f32 -> scalar f32
// Two kernel nodes: main (REDG partials -> g_sum) + 1-thread finalize.

#define D_DIM 256
#define THREADS 256               // 8 warps
#define NW (THREADS / 32)
#define GROUPS 2                  // register double-buffer ping-pong
#define GROUP_ROWS 32             // 8 warps * 4 rows
#define ROWS_PER_BLOCK (GROUPS * GROUP_ROWS)   // 64 -> grid 4096 for N=256K

__device__ float g_sum = 0.0f;    // cross-CTA accumulator (reset by finalize)

__device__ __forceinline__ float4 ldcs4(const float4* p) {
    return __ldcs(p);             // streaming: x bytes are read exactly once
}

// ---- Main: 8 lanes/row, 4 rows/warp, register double-buffer ----
// ALL_VALID=true when N % ROWS_PER_BLOCK == 0 (no bounds checks at all).
template <bool ALL_VALID>
__global__ void __launch_bounds__(THREADS, 3)
inner_cos_kernel(const float* __restrict__ x,
                 const int* __restrict__ lab,
                 const float* __restrict__ cen,
                 int N)
{
    const int tid  = threadIdx.x;
    const int lane = tid & 31;
    const int warp = tid >> 5;
    const int sub  = lane >> 3;   // warp's row 0..3 within a group
    const int sl   = lane & 7;    // owns 8 float4 of the row

    const int rbase = blockIdx.x * ROWS_PER_BLOCK + warp * 4 + sub;

    float acc = 0.0f;

    // ---- pipeline prologue: group 0 loads ----
    const int r0 = rbase;
    int lb = (ALL_VALID || r0 < N) ? __ldg(lab + r0) : 0;
    float4 a[8];
    {
        const int rc = ALL_VALID ? r0 : min(r0, N - 1);
        const float4* xr = reinterpret_cast<const float4*>(x + (size_t)rc * D_DIM);
        #pragma unroll
        for (int j = 0; j < 8; ++j)
            a[j] = ldcs4(xr + sl + 8 * j);
    }

    #pragma unroll
    for (int it = 0; it < GROUPS; ++it) {
        const bool v      = ALL_VALID || (rbase + it * GROUP_ROWS) < N;
        const int  lb_cur = lb;

        // ---- issue NEXT group's loads first (keep DRAM queue full) ----
        float4 b[8];
        if (it + 1 < GROUPS) {
            const int rn = rbase + (it + 1) * GROUP_ROWS;
            lb = (ALL_VALID || rn < N) ? __ldg(lab + rn) : 0;
            const int rc = ALL_VALID ? rn : min(rn, N - 1);
            const float4* xn = reinterpret_cast<const float4*>(x + (size_t)rc * D_DIM);
            #pragma unroll
            for (int j = 0; j < 8; ++j)
                b[j] = ldcs4(xn + sl + 8 * j);
        }

        // ---- compute on CURRENT group: dot, ||x||^2, ||c||^2 inline ----
        const float4* cr = reinterpret_cast<const float4*>(
            cen + (size_t)lb_cur * D_DIM);

        float dot0 = 0.f, dot1 = 0.f, nx0 = 0.f, nx1 = 0.f, nc0 = 0.f, nc1 = 0.f;
        #pragma unroll
        for (int j = 0; j < 8; j += 2) {
            float4 c0 = __ldg(cr + sl + 8 * j);        // L1-resident
            float4 c1 = __ldg(cr + sl + 8 * (j + 1));
            dot0 = fmaf(a[j].x, c0.x, fmaf(a[j].y, c0.y,
                   fmaf(a[j].z, c0.z, fmaf(a[j].w, c0.w, dot0))));
            nx0  = fmaf(a[j].x, a[j].x, fmaf(a[j].y, a[j].y,
                   fmaf(a[j].z, a[j].z, fmaf(a[j].w, a[j].w, nx0))));
            nc0  = fmaf(c0.x, c0.x, fmaf(c0.y, c0.y,
                   fmaf(c0.z, c0.z, fmaf(c0.w, c0.w, nc0))));
            dot1 = fmaf(a[j+1].x, c1.x, fmaf(a[j+1].y, c1.y,
                   fmaf(a[j+1].z, c1.z, fmaf(a[j+1].w, c1.w, dot1))));
            nx1  = fmaf(a[j+1].x, a[j+1].x, fmaf(a[j+1].y, a[j+1].y,
                   fmaf(a[j+1].z, a[j+1].z, fmaf(a[j+1].w, a[j+1].w, nx1))));
            nc1  = fmaf(c1.x, c1.x, fmaf(c1.y, c1.y,
                   fmaf(c1.z, c1.z, fmaf(c1.w, c1.w, nc1))));
        }
        float dot = dot0 + dot1;
        float nx2 = nx0 + nx1;
        float nc2 = nc0 + nc1;

        #pragma unroll
        for (int o = 4; o > 0; o >>= 1) {      // reduce across the 8-lane group
            dot += __shfl_xor_sync(0xffffffffu, dot, o);
            nx2 += __shfl_xor_sync(0xffffffffu, nx2, o);
            nc2 += __shfl_xor_sync(0xffffffffu, nc2, o);
        }

        if (sl == 0 && v) {
            // cos = dot / max(||x||*||c||, 1e-8)  ==  dot * rsqrt(max(nx2*nc2, 1e-16))
            float cos = dot * rsqrtf(fmaxf(nx2 * nc2, 1e-16f));
            acc += fminf(fmaxf(1.0f - cos, 1e-12f), 1e12f);
        }

        // ---- rotate pipeline ----
        if (it + 1 < GROUPS) {
            #pragma unroll
            for (int j = 0; j < 8; ++j) a[j] = b[j];
        }
    }

    // ---- warp reduce (acc nonzero only on sl==0 lanes), block reduce ----
    #pragma unroll
    for (int o = 16; o > 0; o >>= 1)
        acc += __shfl_xor_sync(0xffffffffu, acc, o);

    __shared__ float wsum[NW];
    if (lane == 0) wsum[warp] = acc;
    __syncthreads();
    if (tid == 0) {
        float s = 0.0f;
        #pragma unroll
        for (int i = 0; i < NW; ++i) s += wsum[i];
        atomicAdd(&g_sum, s);     // return unused -> REDG, fire-and-forget
    }
}

// ---- Finalize node: write output, reset accumulator for next replay ----
__global__ void finalize_kernel(float* __restrict__ out, float invN)
{
    *out  = g_sum * invN;         // REDG results visible at kernel boundary
    g_sum = 0.0f;                 // restore initial state for next replay
}

extern "C" void kernel_launch(void* const* d_in, const int* in_sizes, int n_in,
                              void* d_out, int out_size)
{
    const float* x   = (const float*)d_in[0];   // ref_emb [N, 256]
    const int*   lab = (const int*)d_in[1];     // ref_label [N]
    const float* cen = (const float*)d_in[2];   // centers [C, 256]
    float* out = (float*)d_out;

    const int N = in_sizes[1];
    const int blocks = (N + ROWS_PER_BLOCK - 1) / ROWS_PER_BLOCK;
    const float invN = 1.0f / (float)N;

    if (N % ROWS_PER_BLOCK == 0)
        inner_cos_kernel<true><<<blocks, THREADS>>>(x, lab, cen, N);
    else
        inner_cos_kernel<false><<<blocks, THREADS>>>(x, lab, cen, N);

    finalize_kernel<<<1, 1>>>(out, invN);
}